// round 1
// baseline (speedup 1.0000x reference)
#include <cuda_runtime.h>

// Problem: x[64, 64, 64, 128] fp32.
//   out1 = FWHT along axis 1 (i, length 64)
//   out2 = FWHT along axis 2 (j, length 64) of out1
// d_out = [out1 | out2] concatenated (tuple order), 2 * 64^3 * 128 floats.

#define DIM_B 64
#define DIM_I 64
#define DIM_J 64
#define DIM_C 128
#define CCHUNK 8              // 8 fp32 channels = 32 B = one DRAM sector
#define ROWF 520              // smem row stride in floats (64*8 + 8 pad) -> conflict-free both patterns
#define THREADS 512
#define SMEM_BYTES (DIM_I * ROWF * 4)   // 133,120 B

__global__ __launch_bounds__(THREADS, 1)
void wht2_kernel(const float* __restrict__ x,
                 float* __restrict__ out1,
                 float* __restrict__ out2)
{
    extern __shared__ float sm[];

    const int b  = blockIdx.x >> 4;          // 64 batches
    const int cc = blockIdx.x & 15;          // 16 channel chunks
    const int c0 = cc * CCHUNK;
    const int t  = threadIdx.x;

    const size_t base = (size_t)b * (DIM_I * DIM_J * DIM_C);

    // ---------- stage-in: gmem -> smem, fully coalesced float4 ----------
    // linear index over (i, j, half): each (i,j) is 8 floats = 2 float4
#pragma unroll
    for (int r = 0; r < 16; r++) {
        int lin  = r * THREADS + t;          // 0..8191
        int half = lin & 1;
        int j    = (lin >> 1) & 63;
        int i    = lin >> 7;
        const float4 val = *reinterpret_cast<const float4*>(
            x + base + (size_t)i * (DIM_J * DIM_C) + j * DIM_C + c0 + half * 4);
        *reinterpret_cast<float4*>(sm + i * ROWF + j * 8 + half * 4) = val;
    }
    __syncthreads();

    float v[64];

    // ---------- phase A: FWHT over i, register-resident ----------
    {
        const int c   = t & 7;
        const int j   = t >> 3;              // 0..63
        const int off = j * 8 + c;
#pragma unroll
        for (int i = 0; i < 64; i++) v[i] = sm[i * ROWF + off];

#pragma unroll
        for (int h = 1; h < 64; h <<= 1) {
#pragma unroll
            for (int s = 0; s < 64; s += 2 * h) {
#pragma unroll
                for (int k = 0; k < h; k++) {
                    float a  = v[s + k];
                    float bb = v[s + k + h];
                    v[s + k]     = a + bb;
                    v[s + k + h] = a - bb;
                }
            }
        }

#pragma unroll
        for (int i = 0; i < 64; i++) sm[i * ROWF + off] = v[i];
    }
    __syncthreads();

    // ---------- store out1: smem -> gmem, coalesced float4 ----------
#pragma unroll
    for (int r = 0; r < 16; r++) {
        int lin  = r * THREADS + t;
        int half = lin & 1;
        int j    = (lin >> 1) & 63;
        int i    = lin >> 7;
        float4 val = *reinterpret_cast<float4*>(sm + i * ROWF + j * 8 + half * 4);
        *reinterpret_cast<float4*>(
            out1 + base + (size_t)i * (DIM_J * DIM_C) + j * DIM_C + c0 + half * 4) = val;
    }

    // ---------- phase B: FWHT over j, register-resident ----------
    // (reads of H_i data overlap the out1 store; sync before overwriting smem)
    {
        const int c      = t & 7;
        const int i      = t >> 3;           // 0..63
        const int rowoff = i * ROWF + c;
#pragma unroll
        for (int j = 0; j < 64; j++) v[j] = sm[rowoff + j * 8];

#pragma unroll
        for (int h = 1; h < 64; h <<= 1) {
#pragma unroll
            for (int s = 0; s < 64; s += 2 * h) {
#pragma unroll
                for (int k = 0; k < h; k++) {
                    float a  = v[s + k];
                    float bb = v[s + k + h];
                    v[s + k]     = a + bb;
                    v[s + k + h] = a - bb;
                }
            }
        }

        __syncthreads();   // all out1-store LDS + phase-B LDS done before overwrite
#pragma unroll
        for (int j = 0; j < 64; j++) sm[rowoff + j * 8] = v[j];
    }
    __syncthreads();

    // ---------- store out2: smem -> gmem, coalesced float4 ----------
#pragma unroll
    for (int r = 0; r < 16; r++) {
        int lin  = r * THREADS + t;
        int half = lin & 1;
        int j    = (lin >> 1) & 63;
        int i    = lin >> 7;
        float4 val = *reinterpret_cast<float4*>(sm + i * ROWF + j * 8 + half * 4);
        *reinterpret_cast<float4*>(
            out2 + base + (size_t)i * (DIM_J * DIM_C) + j * DIM_C + c0 + half * 4) = val;
    }
}

extern "C" void kernel_launch(void* const* d_in, const int* in_sizes, int n_in,
                              void* d_out, int out_size)
{
    const float* x = (const float*)d_in[0];
    float* out = (float*)d_out;
    const size_t N1 = (size_t)DIM_B * DIM_I * DIM_J * DIM_C;  // 33,554,432

    cudaFuncSetAttribute(wht2_kernel,
                         cudaFuncAttributeMaxDynamicSharedMemorySize, SMEM_BYTES);

    wht2_kernel<<<DIM_B * (DIM_C / CCHUNK), THREADS, SMEM_BYTES>>>(x, out, out + N1);
}

// round 2
// speedup vs baseline: 1.3344x; 1.3344x over previous
#include <cuda_runtime.h>

// x[64, 64, 64, 128] fp32.
//   out1 = FWHT along axis 1 (i, len 64)   : element stride 64*128 = 8192
//   out2 = FWHT along axis 2 (j, len 64) of out1 : element stride 128
// d_out = [out1 | out2], 2 * 64^3 * 128 floats.
//
// Strategy: one thread per scalar "column" along the transform axis.
// Loads/stores are perfectly coalesced (consecutive threads = consecutive
// addresses); the length-64 butterfly runs entirely in registers.
// No shared memory, no barriers -> pure streaming, DRAM-bound.

#define THREADS 256
#define NCOLS (64u * 64u * 64u * 128u / 64u)   // 2^19 columns per kernel

template <int STRIDE>
__global__ __launch_bounds__(THREADS)
void fwht_axis_kernel(const float* __restrict__ in, float* __restrict__ out)
{
    // Columns with the same outer index share a contiguous span of STRIDE
    // elements; each outer group spans 64*STRIDE elements.
    const unsigned g = blockIdx.x * THREADS + threadIdx.x;   // 0 .. 2^19-1
    const size_t base = (size_t)(g / STRIDE) * (64u * STRIDE) + (g % STRIDE);

    float v[64];
#pragma unroll
    for (int k = 0; k < 64; k++)
        v[k] = in[base + (size_t)k * STRIDE];

#pragma unroll
    for (int h = 1; h < 64; h <<= 1) {
#pragma unroll
        for (int s = 0; s < 64; s += 2 * h) {
#pragma unroll
            for (int k = 0; k < h; k++) {
                float a = v[s + k];
                float b = v[s + k + h];
                v[s + k]     = a + b;
                v[s + k + h] = a - b;
            }
        }
    }

#pragma unroll
    for (int k = 0; k < 64; k++)
        out[base + (size_t)k * STRIDE] = v[k];
}

extern "C" void kernel_launch(void* const* d_in, const int* in_sizes, int n_in,
                              void* d_out, int out_size)
{
    const float* x = (const float*)d_in[0];
    float* out1 = (float*)d_out;
    float* out2 = out1 + (size_t)64 * 64 * 64 * 128;

    const unsigned grid = NCOLS / THREADS;   // 2048

    // axis 1: stride J*C = 8192
    fwht_axis_kernel<8192><<<grid, THREADS>>>(x, out1);
    // axis 2: stride C = 128 (reads out1)
    fwht_axis_kernel<128><<<grid, THREADS>>>(out1, out2);
}